// round 17
// baseline (speedup 1.0000x reference)
#include <cuda_runtime.h>
#include <math.h>

#define Bb 32
#define Tt 128
#define Ll 512
#define Dd 256
#define VOC 32000

#define FFMA2(acc, a, b) asm("fma.rn.f32x2 %0, %1, %2, %0;" : "+l"(acc) : "l"(a), "l"(b))
#define DUP2(dst, s)     asm("mov.b64 %0, {%1, %1};" : "=l"(dst) : "f"(s))

// ---------------- scratch ----------------
__device__ float g_x[Tt*Bb*Dd];             // [t*B+b][d]
__device__ float g_gx[2][Tt*Bb*768];        // [dir][t*B+b][gate*256+d]
__device__ float g_hbuf[2][2][Bb*Dd];       // [dir][parity][b*256+d]
__device__ float g_outext[4224*512];        // rows b*T+t = outputs ; rows 4096+b = [hT_f|hT_b]
__device__ float g_roext[4224*256];         // rows b*T+t = rnn_out ; rows 4096+b = hidden
__device__ float g_E[4][Bb*Ll*Dd];          // embed_bag + add_lm per table
__device__ float g_u[Bb*Dd];
__device__ unsigned g_bar[2];

// ---------------- init ----------------
__global__ void k_init() {
    int tid = threadIdx.x;
    for (int i = tid; i < Bb*Dd; i += 256) { g_hbuf[0][0][i] = 0.f; g_hbuf[1][0][i] = 0.f; }
    if (tid < 2) g_bar[tid] = 0u;
}

// ---------------- conv embed-bag -> x[T,B,D] ----------------
__global__ void k_embed_conv(const int* __restrict__ conv, const float* __restrict__ tab) {
    int bid = blockIdx.x;                  // b*T + t
    int b = bid >> 7, t = bid & 127;
    int d = threadIdx.x;
    const int* ip = conv + (size_t)bid * 4;
    float s = tab[(size_t)ip[0]*Dd + d] + tab[(size_t)ip[1]*Dd + d]
            + tab[(size_t)ip[2]*Dd + d] + tab[(size_t)ip[3]*Dd + d];
    g_x[((size_t)t*Bb + b)*Dd + d] = s;
}

// ---------------- GEMM: C[M,N] = A[M,K] * Bw[N,K]^T + bias (FFMA2, reg-dup) ----------------
// mode 0: A=g_x (4096x256) -> g_gx[blockIdx.z] (N=768), weights selected by z
// mode 2: A=g_outext (4224x512) -> g_roext (N=256)
__global__ __launch_bounds__(256) void k_gemm(const float* __restrict__ Bw,
                                              const float* __restrict__ bias,
                                              const float* __restrict__ Bw2,
                                              const float* __restrict__ bias2, int mode) {
    __shared__ __align__(16) float as[16][128];
    __shared__ __align__(16) float bs[16][64];
    const float* A; float* C; int Kd, Nd;
    if (mode == 0) {
        if (blockIdx.z == 1) { Bw = Bw2; bias = bias2; }
        A = g_x; C = g_gx[blockIdx.z]; Kd = 256; Nd = 768;
    } else {
        A = g_outext; C = g_roext; Kd = 512; Nd = 256;
    }

    int tid = threadIdx.x;
    int j = tid & 15;
    int i = tid >> 4;
    int bm = blockIdx.x * 128;
    int bn = blockIdx.y * 64;

    unsigned long long acc[8][2];
    #pragma unroll
    for (int r = 0; r < 8; r++) { acc[r][0] = 0ull; acc[r][1] = 0ull; }

    for (int k0 = 0; k0 < Kd; k0 += 16) {
        #pragma unroll
        for (int p = 0; p < 2; p++) {
            int s = tid + p*256;
            int m = s >> 2, kc = s & 3;
            float4 v = *(const float4*)&A[(size_t)(bm + m)*Kd + k0 + kc*4];
            as[kc*4+0][m] = v.x; as[kc*4+1][m] = v.y; as[kc*4+2][m] = v.z; as[kc*4+3][m] = v.w;
        }
        {
            int s = tid;
            int n = s >> 2, kc = s & 3;
            float4 v = *(const float4*)&Bw[(size_t)(bn + n)*Kd + k0 + kc*4];
            bs[kc*4+0][n] = v.x; bs[kc*4+1][n] = v.y; bs[kc*4+2][n] = v.z; bs[kc*4+3][n] = v.w;
        }
        __syncthreads();
        #pragma unroll
        for (int kk = 0; kk < 16; kk++) {
            float4 a0 = *(const float4*)&as[kk][i*8];
            float4 a1 = *(const float4*)&as[kk][i*8+4];
            ulonglong2 bq = *(const ulonglong2*)&bs[kk][j*4];   // (c0,c1),(c2,c3)
            unsigned long long A0,A1,A2,A3,A4,A5,A6,A7;
            DUP2(A0, a0.x); DUP2(A1, a0.y); DUP2(A2, a0.z); DUP2(A3, a0.w);
            DUP2(A4, a1.x); DUP2(A5, a1.y); DUP2(A6, a1.z); DUP2(A7, a1.w);
            FFMA2(acc[0][0], A0, bq.x); FFMA2(acc[0][1], A0, bq.y);
            FFMA2(acc[1][0], A1, bq.x); FFMA2(acc[1][1], A1, bq.y);
            FFMA2(acc[2][0], A2, bq.x); FFMA2(acc[2][1], A2, bq.y);
            FFMA2(acc[3][0], A3, bq.x); FFMA2(acc[3][1], A3, bq.y);
            FFMA2(acc[4][0], A4, bq.x); FFMA2(acc[4][1], A4, bq.y);
            FFMA2(acc[5][0], A5, bq.x); FFMA2(acc[5][1], A5, bq.y);
            FFMA2(acc[6][0], A6, bq.x); FFMA2(acc[6][1], A6, bq.y);
            FFMA2(acc[7][0], A7, bq.x); FFMA2(acc[7][1], A7, bq.y);
        }
        __syncthreads();
    }
    float4 bb = *(const float4*)&bias[bn + j*4];
    #pragma unroll
    for (int r = 0; r < 8; r++) {
        float2 p0 = *(float2*)&acc[r][0];
        float2 p1 = *(float2*)&acc[r][1];
        float4 o;
        o.x = p0.x + bb.x; o.y = p0.y + bb.y;
        o.z = p1.x + bb.z; o.w = p1.y + bb.w;
        *(float4*)&C[(size_t)(bm + i*8 + r)*Nd + bn + j*4] = o;
    }
}

// ---------------- persistent GRU recurrence (FFMA2 dot, fast activations) ----------------
__global__ __launch_bounds__(128) void k_recur(const float* __restrict__ Whh_f,
                                               const float* __restrict__ bhh_f,
                                               const float* __restrict__ Whh_b,
                                               const float* __restrict__ bhh_b) {
    int dir = blockIdx.x >> 6;
    int cid = blockIdx.x & 63;
    int d0 = cid * 4;
    const float* Whh = dir ? Whh_b : Whh_f;
    const float* bhh = dir ? bhh_b : bhh_f;

    __shared__ float sW[12][260];
    __shared__ float sh[32][260];

    int tid = threadIdx.x;
    int lane = tid & 31;       // b
    int j = tid >> 5;          // 0..3
    int d = d0 + j;

    for (int r = 0; r < 12; r++) {
        int g = r >> 2, jj = r & 3;
        for (int k = tid; k < 256; k += 128)
            sW[r][k] = Whh[(size_t)(g*256 + d0 + jj)*256 + k];
    }
    float br = bhh[d], bz = bhh[256+d], bnb = bhh[512+d];
    __syncthreads();

    for (int t = 0; t < 128; t++) {
        int tx = dir ? (127 - t) : t;
        const float* gx = &g_gx[dir][((size_t)tx*Bb + lane)*768];
        float xr = __ldg(&gx[d]), xz = __ldg(&gx[256+d]), xn = __ldg(&gx[512+d]);

        const float4* hg = (const float4*)g_hbuf[dir][t & 1];
        for (int s = tid; s < 2048; s += 128) {
            float4 v = __ldcg(&hg[s]);
            int b = s >> 6, c = s & 63;
            *((float4*)&sh[b][0] + c) = v;
        }
        __syncthreads();

        unsigned long long ar2[2] = {0ull,0ull}, az2[2] = {0ull,0ull}, an2[2] = {0ull,0ull};
        const ulonglong2* h2  = (const ulonglong2*)&sh[lane][0];
        const ulonglong2* wr2 = (const ulonglong2*)&sW[0 + j][0];
        const ulonglong2* wz2 = (const ulonglong2*)&sW[4 + j][0];
        const ulonglong2* wn2 = (const ulonglong2*)&sW[8 + j][0];
        #pragma unroll 8
        for (int c = 0; c < 64; c++) {
            ulonglong2 hv = h2[c];
            ulonglong2 wv = wr2[c];
            FFMA2(ar2[0], hv.x, wv.x); FFMA2(ar2[1], hv.y, wv.y);
            wv = wz2[c];
            FFMA2(az2[0], hv.x, wv.x); FFMA2(az2[1], hv.y, wv.y);
            wv = wn2[c];
            FFMA2(an2[0], hv.x, wv.x); FFMA2(an2[1], hv.y, wv.y);
        }
        float2 fa, fb;
        fa = *(float2*)&ar2[0]; fb = *(float2*)&ar2[1];
        float ar = (fa.x + fa.y) + (fb.x + fb.y);
        fa = *(float2*)&az2[0]; fb = *(float2*)&az2[1];
        float az = (fa.x + fa.y) + (fb.x + fb.y);
        fa = *(float2*)&an2[0]; fb = *(float2*)&an2[1];
        float an = (fa.x + fa.y) + (fb.x + fb.y);

        // fast activations (ex2.approx-based, ~1e-7 rel err)
        float rr = __fdividef(1.f, 1.f + __expf(-(xr + ar + br)));
        float zz = __fdividef(1.f, 1.f + __expf(-(xz + az + bz)));
        float pn = xn + rr*(an + bnb);
        pn = fminf(fmaxf(pn, -15.f), 15.f);
        float e2 = __expf(2.f*pn);
        float nn = __fdividef(e2 - 1.f, e2 + 1.f);
        float hprev = sh[lane][d];
        float hnew = (1.f - zz)*nn + zz*hprev;

        g_hbuf[dir][(t + 1) & 1][lane*Dd + d] = hnew;
        g_outext[((size_t)lane*Tt + tx)*512 + dir*256 + d] = hnew;   // fused pack
        if (t == 127)
            g_outext[(size_t)(4096 + lane)*512 + dir*256 + d] = hnew;

        __threadfence();
        __syncthreads();
        if (tid == 0) {
            atomicAdd(&g_bar[dir], 1u);
            unsigned target = (unsigned)(t + 1) * 64u;
            while (*((volatile unsigned*)&g_bar[dir]) < target) { }
        }
        __syncthreads();
    }
}

// ---------------- memory embed-bag + add_lm (fused over 4 tables) ----------------
__global__ void k_embed_mem(const int* __restrict__ src, const float* __restrict__ Ct,
                            const int* __restrict__ kb, const int* __restrict__ cl) {
    int bid = blockIdx.x;                 // b*512 + l
    int d = threadIdx.x;
    int b = bid >> 9, l = bid & 511;
    const int* ip = src + (size_t)bid * 4;
    int i0 = ip[0], i1 = ip[1], i2 = ip[2], i3 = ip[3];
    int rel = l - kb[b];
    float add = (rel >= 0 && rel < cl[b]) ? g_roext[((size_t)b*Tt + rel)*Dd + d] : 0.f;
    #pragma unroll
    for (int k = 0; k < 4; k++) {
        const float* tab = Ct + (size_t)k*VOC*Dd;
        float s = tab[(size_t)i0*Dd + d] + tab[(size_t)i1*Dd + d]
                + tab[(size_t)i2*Dd + d] + tab[(size_t)i3*Dd + d];
        g_E[k][(size_t)bid*Dd + d] = s + add;
    }
}

// ---------------- fused 3-hop memory kernel: one CTA per batch row ----------------
__global__ __launch_bounds__(256) void k_hops(float* __restrict__ out) {
    __shared__ float su[256];
    __shared__ float sl[512];
    __shared__ float red[8];
    __shared__ float4 sok[4][64];
    int b = blockIdx.x;
    int tid = threadIdx.x;
    int lane = tid & 31, w = tid >> 5;

    su[tid] = g_roext[(size_t)(4096 + b)*Dd + tid];   // hidden
    __syncthreads();

    for (int h = 0; h < 3; h++) {
        // ---- logits: warp w computes l = w*64 .. w*64+63 ----
        const float4* u4 = (const float4*)su;
        float4 ua = u4[lane*2], ub = u4[lane*2 + 1];  // u[lane*8 .. lane*8+7]
        #pragma unroll 4
        for (int l = w*64; l < w*64 + 64; l++) {
            const float4* E4 = (const float4*)(g_E[h] + ((size_t)(b*Ll + l))*Dd);
            float4 e0 = E4[lane*2], e1 = E4[lane*2 + 1];
            float s = e0.x*ua.x + e0.y*ua.y + e0.z*ua.z + e0.w*ua.w
                    + e1.x*ub.x + e1.y*ub.y + e1.z*ub.z + e1.w*ub.w;
            #pragma unroll
            for (int o = 16; o; o >>= 1) s += __shfl_down_sync(0xffffffffu, s, o);
            if (lane == 0) sl[l] = s;
        }
        __syncthreads();

        // ---- softmax over sl[512] (+ sigmoid output at final hop) ----
        float v0 = sl[tid], v1 = sl[tid + 256];
        if (h == 2) {
            out[b*Ll + tid]       = __fdividef(1.f, 1.f + __expf(-v0));
            out[b*Ll + tid + 256] = __fdividef(1.f, 1.f + __expf(-v1));
        }
        float m = fmaxf(v0, v1);
        #pragma unroll
        for (int o = 16; o; o >>= 1) m = fmaxf(m, __shfl_xor_sync(0xffffffffu, m, o));
        if (lane == 0) red[w] = m;
        __syncthreads();
        m = red[0];
        #pragma unroll
        for (int k = 1; k < 8; k++) m = fmaxf(m, red[k]);
        float e0 = __expf(v0 - m), e1 = __expf(v1 - m);
        float ss = e0 + e1;
        #pragma unroll
        for (int o = 16; o; o >>= 1) ss += __shfl_xor_sync(0xffffffffu, ss, o);
        __syncthreads();
        if (lane == 0) red[w] = ss;
        __syncthreads();
        float tot = ((red[0] + red[1]) + (red[2] + red[3]))
                  + ((red[4] + red[5]) + (red[6] + red[7]));
        float inv = __fdividef(1.f, tot);
        sl[tid] = e0 * inv; sl[tid + 256] = e1 * inv;
        __syncthreads();

        // ---- o_k: chunk of 128 l per thread-quarter, float4 over d ----
        int chunk = tid >> 6, dq = tid & 63;
        const float4* Ec4 = (const float4*)(g_E[h+1] + (size_t)b*Ll*Dd) + dq;
        float4 acc = make_float4(0.f, 0.f, 0.f, 0.f);
        #pragma unroll 8
        for (int l = chunk*128; l < chunk*128 + 128; l++) {
            float4 ev = Ec4[(size_t)l*64];
            float p = sl[l];
            acc.x += ev.x*p; acc.y += ev.y*p; acc.z += ev.z*p; acc.w += ev.w*p;
        }
        sok[chunk][dq] = acc;
        __syncthreads();
        const float* pf = (const float*)sok;
        float newu = su[tid] + ((pf[tid] + pf[256 + tid]) + (pf[512 + tid] + pf[768 + tid]));
        __syncthreads();
        su[tid] = newu;
        __syncthreads();
    }
    g_u[b*Dd + tid] = su[tid];
}

// ---------------- final projection ----------------
__global__ void k_proj(const float* __restrict__ pw, const float* __restrict__ pb,
                       float* __restrict__ out) {
    int wid = blockIdx.x*8 + (threadIdx.x >> 5);   // 0..8191
    int lane = threadIdx.x & 31;
    int b = wid >> 8, d = wid & 255;
    const float4* w4 = (const float4*)(pw + (size_t)d*512);
    const float4* h4 = (const float4*)(g_roext + (size_t)(4096 + b)*Dd);
    const float4* u4 = (const float4*)(g_u + b*Dd);
    float4 wv, av; float s = 0.f;
    wv = w4[lane];      av = h4[lane];      s += wv.x*av.x + wv.y*av.y + wv.z*av.z + wv.w*av.w;
    wv = w4[lane+32];   av = h4[lane+32];   s += wv.x*av.x + wv.y*av.y + wv.z*av.z + wv.w*av.w;
    wv = w4[lane+64];   av = u4[lane];      s += wv.x*av.x + wv.y*av.y + wv.z*av.z + wv.w*av.w;
    wv = w4[lane+96];   av = u4[lane+32];   s += wv.x*av.x + wv.y*av.y + wv.z*av.z + wv.w*av.w;
    #pragma unroll
    for (int o = 16; o; o >>= 1) s += __shfl_down_sync(0xffffffffu, s, o);
    if (lane == 0) out[16384 + b*Dd + d] = fmaxf(0.f, s + pb[d]);
}

// ---------------- launch ----------------
extern "C" void kernel_launch(void* const* d_in, const int* in_sizes, int n_in,
                              void* d_out, int out_size) {
    (void)in_sizes; (void)n_in; (void)out_size;
    const int*   conv    = (const int*)d_in[0];
    const int*   src     = (const int*)d_in[1];
    const int*   kb      = (const int*)d_in[2];
    const int*   cl      = (const int*)d_in[3];
    const float* emb_ctx = (const float*)d_in[4];
    const float* Ct      = (const float*)d_in[5];
    const float* Wih_f   = (const float*)d_in[6];
    const float* Whh_f   = (const float*)d_in[7];
    const float* bih_f   = (const float*)d_in[8];
    const float* bhh_f   = (const float*)d_in[9];
    const float* Wih_b   = (const float*)d_in[10];
    const float* Whh_b   = (const float*)d_in[11];
    const float* bih_b   = (const float*)d_in[12];
    const float* bhh_b   = (const float*)d_in[13];
    const float* W_w     = (const float*)d_in[14];
    const float* W_b     = (const float*)d_in[15];
    const float* proj_w  = (const float*)d_in[16];
    const float* proj_b  = (const float*)d_in[17];
    float* out = (float*)d_out;

    k_init<<<1, 256>>>();
    k_embed_conv<<<4096, 256>>>(conv, emb_ctx);
    k_gemm<<<dim3(32, 12, 2), 256>>>(Wih_f, bih_f, Wih_b, bih_b, 0);
    k_recur<<<128, 128>>>(Whh_f, bhh_f, Whh_b, bhh_b);
    k_gemm<<<dim3(33, 4, 1), 256>>>(W_w, W_b, nullptr, nullptr, 2);
    k_embed_mem<<<16384, 256>>>(src, Ct, kb, cl);
    k_hops<<<32, 256>>>(out);
    k_proj<<<1024, 256>>>(proj_w, proj_b, out);
}